// round 14
// baseline (speedup 1.0000x reference)
#include <cuda_runtime.h>
#include <cuda_fp16.h>
#include <math.h>

// Problem constants
static constexpr int NB   = 256;
static constexpr int NS   = 512;
static constexpr int NH   = 512;
static constexpr int NE   = 512;
static constexpr int NV   = 50257;
static constexpr int NENC = 1024;   // 2*H

static constexpr int SCHUNKS = 8;

// Scratch
__device__ float g_pgen[NB];
__device__ float g_dotp[SCHUNKS * NB];
__device__ int   g_ids_is64;

// ---------------------------------------------------------------------------
// helpers
// ---------------------------------------------------------------------------
__device__ __forceinline__ unsigned smem_u32(const void* p) {
    unsigned a;
    asm("{ .reg .u64 t; cvta.to.shared.u64 t, %1; cvt.u32.u64 %0, t; }"
        : "=r"(a) : "l"(p));
    return a;
}
__device__ __forceinline__ float warp_reduce_max(float v) {
    #pragma unroll
    for (int o = 16; o > 0; o >>= 1) v = fmaxf(v, __shfl_xor_sync(0xffffffffu, v, o));
    return v;
}
__device__ __forceinline__ float warp_reduce_sum(float v) {
    #pragma unroll
    for (int o = 16; o > 0; o >>= 1) v += __shfl_xor_sync(0xffffffffu, v, o);
    return v;
}

__device__ __forceinline__ void ldsm_x4(unsigned* r, unsigned addr) {
    asm volatile("ldmatrix.sync.aligned.m8n8.x4.shared.b16 {%0,%1,%2,%3}, [%4];"
                 : "=r"(r[0]), "=r"(r[1]), "=r"(r[2]), "=r"(r[3]) : "r"(addr));
}
__device__ __forceinline__ void mma_f16(float* d, const unsigned* a, const unsigned* b) {
    asm volatile(
        "mma.sync.aligned.m16n8k16.row.col.f32.f16.f16.f32 "
        "{%0,%1,%2,%3}, {%4,%5,%6,%7}, {%8,%9}, {%0,%1,%2,%3};"
        : "+f"(d[0]), "+f"(d[1]), "+f"(d[2]), "+f"(d[3])
        : "r"(a[0]), "r"(a[1]), "r"(a[2]), "r"(a[3]), "r"(b[0]), "r"(b[1]));
}

// fp32x4 -> fp16x4, store as uint2
__device__ __forceinline__ void cvt_store_f16(char* base, unsigned off, float4 w) {
    __half2 p0 = __floats2half2_rn(w.x, w.y);
    __half2 p1 = __floats2half2_rn(w.z, w.w);
    uint2 v;
    v.x = *reinterpret_cast<unsigned*>(&p0);
    v.y = *reinterpret_cast<unsigned*>(&p1);
    *reinterpret_cast<uint2*>(base + off) = v;
}

// ---------------------------------------------------------------------------
// K0: int64-vs-int32 probe for input_ids
// ---------------------------------------------------------------------------
__global__ void detect_ids_kernel(const int* __restrict__ ids32) {
    int tid = threadIdx.x;
    int nz = 0;
    for (int i = tid; i < 4096; i += 256)
        nz |= (ids32[2 * i + 1] != 0);
    nz = __syncthreads_or(nz);
    if (tid == 0) g_ids_is64 = nz ? 0 : 1;
}

// ---------------------------------------------------------------------------
// K1a: partial context dot for p_gen (streams 537 MB)
// ---------------------------------------------------------------------------
__global__ void ctx_partial_kernel(const float* __restrict__ attn,
                                   const float* __restrict__ enc,
                                   const float* __restrict__ pgen_w) {
    const int b = blockIdx.x;
    const int chunk = blockIdx.y;
    const int tid = threadIdx.x;
    const int s0 = chunk * (NS / SCHUNKS);
    __shared__ float s_attn[NS / SCHUNKS];
    __shared__ float red[8];

    for (int i = tid; i < NS / SCHUNKS; i += 256) s_attn[i] = attn[b * NS + s0 + i];
    __syncthreads();

    float4 acc = make_float4(0.f, 0.f, 0.f, 0.f);
    #pragma unroll 4
    for (int s = 0; s < NS / SCHUNKS; s++) {
        const float a = s_attn[s];
        const float4 e = reinterpret_cast<const float4*>(
            enc + ((size_t)(s0 + s) * NB + b) * NENC)[tid];
        acc.x += a * e.x; acc.y += a * e.y; acc.z += a * e.z; acc.w += a * e.w;
    }
    const float* pwc = pgen_w + NH + NE + 4 * tid;
    float dot = acc.x * pwc[0] + acc.y * pwc[1] + acc.z * pwc[2] + acc.w * pwc[3];
    dot = warp_reduce_sum(dot);
    if ((tid & 31) == 0) red[tid >> 5] = dot;
    __syncthreads();
    if (tid == 0) {
        float t = 0.f;
        #pragma unroll
        for (int i = 0; i < 8; i++) t += red[i];
        g_dotp[chunk * NB + b] = t;
    }
}

// ---------------------------------------------------------------------------
// K1b: p_gen
// ---------------------------------------------------------------------------
__global__ void pgen_kernel(const float* __restrict__ hidden,
                            const float* __restrict__ embed,
                            const float* __restrict__ pgen_w,
                            const float* __restrict__ pgen_b) {
    const int b = blockIdx.x;
    const int tid = threadIdx.x;
    __shared__ float red[8];
    const int i0 = 2 * tid;
    float dot = hidden[b * NH + i0]     * pgen_w[i0]
              + hidden[b * NH + i0 + 1] * pgen_w[i0 + 1]
              + embed[b * NE + i0]      * pgen_w[NH + i0]
              + embed[b * NE + i0 + 1]  * pgen_w[NH + i0 + 1];
    dot = warp_reduce_sum(dot);
    if ((tid & 31) == 0) red[tid >> 5] = dot;
    __syncthreads();
    if (tid == 0) {
        float t = 0.f;
        #pragma unroll
        for (int i = 0; i < 8; i++) t += red[i];
        #pragma unroll
        for (int c = 0; c < SCHUNKS; c++) t += g_dotp[c * NB + b];
        t += pgen_b[0];
        g_pgen[b] = 1.f / (1.f + __expf(-t));
    }
}

// ---------------------------------------------------------------------------
// K2: logits via mma.sync fp16 GEMM (single term; ~5e-4 logit rms error,
// far under the 1e-3 gate after log-softmax).
// CTA tile 128(M)x128(N)x32(K), 8 warps (2Mx4N), warp tile 64x32.
// Smem rows padded to 80B -> conflict-free ldmatrix. Double-buffered.
// ---------------------------------------------------------------------------
static constexpr int BM = 128, BN = 128, BK = 32;
static constexpr int TSTR = 80;             // bytes per 32-f16 row (64B data + 16B pad)
static constexpr int TILE = BM * TSTR;      // 10240 B
static constexpr int BUF  = 2 * TILE;       // A, B
static constexpr int GSMEM = 2 * BUF;       // 40960 B

__global__ __launch_bounds__(256, 2)
void gemm_mma_kernel(const float* __restrict__ X,     // [B, H]
                     const float* __restrict__ W,     // [V, H]
                     const float* __restrict__ bias,  // [V]
                     float* __restrict__ out) {       // [B, V]
    extern __shared__ char sm[];
    __shared__ float s_bias[BN];
    const unsigned smb = smem_u32(sm);
    const int tid  = threadIdx.x;
    const int lane = tid & 31;
    const int wid  = tid >> 5;
    const int m_base = blockIdx.x * BM;     // 0 or 128
    const int n_base = blockIdx.y * BN;
    const int wm = (wid >> 2) * 64;
    const int wn = (wid & 3) * 32;

    float acc[4][4][4] = {};
    float4 stA[4], stB[4];

    // gmem load of one K-chunk into staging regs
    auto ldg = [&](int k0) {
        #pragma unroll
        for (int i = 0; i < 4; i++) {
            int idx = i * 256 + tid;
            int r = idx >> 3, c = idx & 7;
            stA[i] = *reinterpret_cast<const float4*>(X + (size_t)(m_base + r) * NH + k0 + c * 4);
            int v = n_base + r;
            stB[i] = (v < NV)
                ? *reinterpret_cast<const float4*>(W + (size_t)v * NH + k0 + c * 4)
                : make_float4(0.f, 0.f, 0.f, 0.f);
        }
    };
    // convert + store staging regs into smem buffer bsel
    auto sts = [&](int bsel) {
        char* base = sm + bsel * BUF;
        #pragma unroll
        for (int i = 0; i < 4; i++) {
            int idx = i * 256 + tid;
            int r = idx >> 3, c = idx & 7;
            unsigned off = r * TSTR + c * 8;
            cvt_store_f16(base, off, stA[i]);
            cvt_store_f16(base + TILE, off, stB[i]);
        }
    };
    auto compute = [&](int bsel) {
        const unsigned Ah = smb + bsel * BUF;
        const unsigned Bh = Ah + TILE;
        const int arow = wm + (lane & 15);
        const int nrow = wn + (lane & 7) + ((lane & 16) ? 8 : 0);
        #pragma unroll
        for (int kk = 0; kk < BK; kk += 16) {
            const unsigned akb = (kk + ((lane & 16) ? 8 : 0)) * 2;
            const unsigned bkb = (kk + ((lane & 8)  ? 8 : 0)) * 2;
            unsigned ah[4][4], bh[4][2];
            #pragma unroll
            for (int mt = 0; mt < 4; mt++) {
                unsigned ad = Ah + (unsigned)(arow + mt * 16) * TSTR + akb;
                ldsm_x4(ah[mt], ad);
            }
            #pragma unroll
            for (int jp = 0; jp < 2; jp++) {
                unsigned bd = Bh + (unsigned)(nrow + jp * 16) * TSTR + bkb;
                unsigned r[4];
                ldsm_x4(r, bd);
                bh[jp * 2][0] = r[0]; bh[jp * 2][1] = r[1];
                bh[jp * 2 + 1][0] = r[2]; bh[jp * 2 + 1][1] = r[3];
            }
            #pragma unroll
            for (int mt = 0; mt < 4; mt++)
                #pragma unroll
                for (int nt = 0; nt < 4; nt++)
                    mma_f16(acc[mt][nt], ah[mt], bh[nt]);
        }
    };

    ldg(0);
    sts(0);
    __syncthreads();
    #pragma unroll 1
    for (int ck = 1; ck <= NH / BK; ck++) {
        if (ck < NH / BK) ldg(ck * BK);
        compute((ck - 1) & 1);
        if (ck < NH / BK) sts(ck & 1);
        __syncthreads();
    }

    // epilogue
    for (int i = tid; i < BN; i += 256) {
        int v = n_base + i;
        s_bias[i] = (v < NV) ? bias[v] : 0.f;
    }
    __syncthreads();

    const int g  = lane >> 2;
    const int t2 = (lane & 3) * 2;
    #pragma unroll
    for (int mt = 0; mt < 4; mt++) {
        const int m0 = m_base + wm + mt * 16 + g;
        float* row0 = out + (size_t)m0 * NV;
        float* row1 = out + (size_t)(m0 + 8) * NV;
        #pragma unroll
        for (int nt = 0; nt < 4; nt++) {
            const int ncol = wn + nt * 8 + t2;
            const int v = n_base + ncol;
            if (v < NV) {
                const float b0 = s_bias[ncol];
                row0[v] = acc[mt][nt][0] + b0;
                row1[v] = acc[mt][nt][2] + b0;
                if (v + 1 < NV) {
                    const float b1 = s_bias[ncol + 1];
                    row0[v + 1] = acc[mt][nt][1] + b1;
                    row1[v + 1] = acc[mt][nt][3] + b1;
                }
            }
        }
    }
}

// ---------------------------------------------------------------------------
// K3: fused softmax + p_gen mix + scatter + log (row in SMEM).
// exp computed once (cached in smem during the sum pass).
// ---------------------------------------------------------------------------
__global__ void finalize_kernel(float* __restrict__ out,
                                const float* __restrict__ attn,
                                const void* __restrict__ ids_raw) {
    extern __shared__ float row[];
    __shared__ float red[32];
    __shared__ float s_bcast;

    const int b = blockIdx.x;
    const int tid = threadIdx.x;   // 1024
    float* o = out + (size_t)b * NV;

    float m = -INFINITY;
    for (int v = tid; v < NV; v += 1024) {
        float t = o[v];
        row[v] = t;
        m = fmaxf(m, t);
    }
    m = warp_reduce_max(m);
    if ((tid & 31) == 0) red[tid >> 5] = m;
    __syncthreads();
    if (tid < 32) {
        float t = warp_reduce_max(red[tid]);
        if (tid == 0) s_bcast = t;
    }
    __syncthreads();
    m = s_bcast;

    float sum = 0.f;
    for (int v = tid; v < NV; v += 1024) {
        float e = __expf(row[v] - m);
        row[v] = e;
        sum += e;
    }
    sum = warp_reduce_sum(sum);
    __syncthreads();
    if ((tid & 31) == 0) red[tid >> 5] = sum;
    __syncthreads();
    if (tid < 32) {
        float t = warp_reduce_sum(red[tid]);
        if (tid == 0) s_bcast = t;
    }
    __syncthreads();
    sum = s_bcast;

    const float pg = g_pgen[b];
    const float scale = pg / sum;

    for (int v = tid; v < NV; v += 1024) row[v] *= scale;
    __syncthreads();

    if (tid < NS) {
        int id;
        if (g_ids_is64)
            id = (int)reinterpret_cast<const long long*>(ids_raw)[(size_t)b * NS + tid];
        else
            id = reinterpret_cast<const int*>(ids_raw)[(size_t)b * NS + tid];
        atomicAdd(&row[id], (1.f - pg) * attn[b * NS + tid]);
    }
    __syncthreads();

    for (int v = tid; v < NV; v += 1024) o[v] = logf(row[v] + 1e-40f);
}

// ---------------------------------------------------------------------------
// Launch
// ---------------------------------------------------------------------------
extern "C" void kernel_launch(void* const* d_in, const int* in_sizes, int n_in,
                              void* d_out, int out_size) {
    const float* x      = (const float*)d_in[0];
    const float* embed  = (const float*)d_in[1];
    const float* hidden = (const float*)d_in[2];
    const float* enc    = (const float*)d_in[3];
    const float* attn   = (const float*)d_in[4];
    const void*  ids    = d_in[5];
    const float* proj_w = (const float*)d_in[6];
    const float* proj_b = (const float*)d_in[7];
    const float* pgen_w = (const float*)d_in[8];
    const float* pgen_b = (const float*)d_in[9];
    float* out = (float*)d_out;

    detect_ids_kernel<<<1, 256>>>((const int*)ids);

    dim3 gctx(NB, SCHUNKS);
    ctx_partial_kernel<<<gctx, 256>>>(attn, enc, pgen_w);
    pgen_kernel<<<NB, 256>>>(hidden, embed, pgen_w, pgen_b);

    cudaFuncSetAttribute(gemm_mma_kernel,
                         cudaFuncAttributeMaxDynamicSharedMemorySize, GSMEM);
    dim3 gg(NB / BM, (NV + BN - 1) / BN);   // (2, 393): M-halves adjacent -> L2 reuse of W
    gemm_mma_kernel<<<gg, 256, GSMEM>>>(x, proj_w, proj_b, out);

    const int smem_bytes = NV * sizeof(float);
    cudaFuncSetAttribute(finalize_kernel,
                         cudaFuncAttributeMaxDynamicSharedMemorySize, smem_bytes);
    finalize_kernel<<<NB, 1024, smem_bytes>>>(out, attn, ids);
}

// round 15
// speedup vs baseline: 1.0021x; 1.0021x over previous
#include <cuda_runtime.h>
#include <cuda_fp16.h>
#include <math.h>

// Problem constants
static constexpr int NB   = 256;
static constexpr int NS   = 512;
static constexpr int NH   = 512;
static constexpr int NE   = 512;
static constexpr int NV   = 50257;
static constexpr int NENC = 1024;   // 2*H

static constexpr int SCHUNKS = 8;

// Scratch
__device__ float g_pgen[NB];
__device__ float g_dotp[SCHUNKS * NB];
__device__ int   g_ids_is64;

// ---------------------------------------------------------------------------
// helpers
// ---------------------------------------------------------------------------
__device__ __forceinline__ unsigned smem_u32(const void* p) {
    unsigned a;
    asm("{ .reg .u64 t; cvta.to.shared.u64 t, %1; cvt.u32.u64 %0, t; }"
        : "=r"(a) : "l"(p));
    return a;
}
__device__ __forceinline__ float warp_reduce_max(float v) {
    #pragma unroll
    for (int o = 16; o > 0; o >>= 1) v = fmaxf(v, __shfl_xor_sync(0xffffffffu, v, o));
    return v;
}
__device__ __forceinline__ float warp_reduce_sum(float v) {
    #pragma unroll
    for (int o = 16; o > 0; o >>= 1) v += __shfl_xor_sync(0xffffffffu, v, o);
    return v;
}

__device__ __forceinline__ void ldsm_x4(unsigned* r, unsigned addr) {
    asm volatile("ldmatrix.sync.aligned.m8n8.x4.shared.b16 {%0,%1,%2,%3}, [%4];"
                 : "=r"(r[0]), "=r"(r[1]), "=r"(r[2]), "=r"(r[3]) : "r"(addr));
}
__device__ __forceinline__ void mma_f16(float* d, const unsigned* a, const unsigned* b) {
    asm volatile(
        "mma.sync.aligned.m16n8k16.row.col.f32.f16.f16.f32 "
        "{%0,%1,%2,%3}, {%4,%5,%6,%7}, {%8,%9}, {%0,%1,%2,%3};"
        : "+f"(d[0]), "+f"(d[1]), "+f"(d[2]), "+f"(d[3])
        : "r"(a[0]), "r"(a[1]), "r"(a[2]), "r"(a[3]), "r"(b[0]), "r"(b[1]));
}

// fp32x4 -> fp16x4, store as uint2
__device__ __forceinline__ void cvt_store_f16(char* base, unsigned off, float4 w) {
    __half2 p0 = __floats2half2_rn(w.x, w.y);
    __half2 p1 = __floats2half2_rn(w.z, w.w);
    uint2 v;
    v.x = *reinterpret_cast<unsigned*>(&p0);
    v.y = *reinterpret_cast<unsigned*>(&p1);
    *reinterpret_cast<uint2*>(base + off) = v;
}

// ---------------------------------------------------------------------------
// K0: int64-vs-int32 probe for input_ids
// ---------------------------------------------------------------------------
__global__ void detect_ids_kernel(const int* __restrict__ ids32) {
    int tid = threadIdx.x;
    int nz = 0;
    for (int i = tid; i < 4096; i += 256)
        nz |= (ids32[2 * i + 1] != 0);
    nz = __syncthreads_or(nz);
    if (tid == 0) g_ids_is64 = nz ? 0 : 1;
}

// ---------------------------------------------------------------------------
// K1a: partial context dot for p_gen (streams 537 MB)
// ---------------------------------------------------------------------------
__global__ void ctx_partial_kernel(const float* __restrict__ attn,
                                   const float* __restrict__ enc,
                                   const float* __restrict__ pgen_w) {
    const int b = blockIdx.x;
    const int chunk = blockIdx.y;
    const int tid = threadIdx.x;
    const int s0 = chunk * (NS / SCHUNKS);
    __shared__ float s_attn[NS / SCHUNKS];
    __shared__ float red[8];

    for (int i = tid; i < NS / SCHUNKS; i += 256) s_attn[i] = attn[b * NS + s0 + i];
    __syncthreads();

    float4 acc = make_float4(0.f, 0.f, 0.f, 0.f);
    #pragma unroll 4
    for (int s = 0; s < NS / SCHUNKS; s++) {
        const float a = s_attn[s];
        const float4 e = reinterpret_cast<const float4*>(
            enc + ((size_t)(s0 + s) * NB + b) * NENC)[tid];
        acc.x += a * e.x; acc.y += a * e.y; acc.z += a * e.z; acc.w += a * e.w;
    }
    const float* pwc = pgen_w + NH + NE + 4 * tid;
    float dot = acc.x * pwc[0] + acc.y * pwc[1] + acc.z * pwc[2] + acc.w * pwc[3];
    dot = warp_reduce_sum(dot);
    if ((tid & 31) == 0) red[tid >> 5] = dot;
    __syncthreads();
    if (tid == 0) {
        float t = 0.f;
        #pragma unroll
        for (int i = 0; i < 8; i++) t += red[i];
        g_dotp[chunk * NB + b] = t;
    }
}

// ---------------------------------------------------------------------------
// K1b: p_gen
// ---------------------------------------------------------------------------
__global__ void pgen_kernel(const float* __restrict__ hidden,
                            const float* __restrict__ embed,
                            const float* __restrict__ pgen_w,
                            const float* __restrict__ pgen_b) {
    const int b = blockIdx.x;
    const int tid = threadIdx.x;
    __shared__ float red[8];
    const int i0 = 2 * tid;
    float dot = hidden[b * NH + i0]     * pgen_w[i0]
              + hidden[b * NH + i0 + 1] * pgen_w[i0 + 1]
              + embed[b * NE + i0]      * pgen_w[NH + i0]
              + embed[b * NE + i0 + 1]  * pgen_w[NH + i0 + 1];
    dot = warp_reduce_sum(dot);
    if ((tid & 31) == 0) red[tid >> 5] = dot;
    __syncthreads();
    if (tid == 0) {
        float t = 0.f;
        #pragma unroll
        for (int i = 0; i < 8; i++) t += red[i];
        #pragma unroll
        for (int c = 0; c < SCHUNKS; c++) t += g_dotp[c * NB + b];
        t += pgen_b[0];
        g_pgen[b] = 1.f / (1.f + __expf(-t));
    }
}

// ---------------------------------------------------------------------------
// K2: logits via mma.sync fp16 GEMM (single term; ~5e-4 logit rms error,
// far under the 1e-3 gate after log-softmax).
// CTA tile 128(M)x128(N)x32(K), 8 warps (2Mx4N), warp tile 64x32.
// Smem rows padded to 80B -> conflict-free ldmatrix. Double-buffered.
// ---------------------------------------------------------------------------
static constexpr int BM = 128, BN = 128, BK = 32;
static constexpr int TSTR = 80;             // bytes per 32-f16 row (64B data + 16B pad)
static constexpr int TILE = BM * TSTR;      // 10240 B
static constexpr int BUF  = 2 * TILE;       // A, B
static constexpr int GSMEM = 2 * BUF;       // 40960 B

__global__ __launch_bounds__(256, 2)
void gemm_mma_kernel(const float* __restrict__ X,     // [B, H]
                     const float* __restrict__ W,     // [V, H]
                     const float* __restrict__ bias,  // [V]
                     float* __restrict__ out) {       // [B, V]
    extern __shared__ char sm[];
    __shared__ float s_bias[BN];
    const unsigned smb = smem_u32(sm);
    const int tid  = threadIdx.x;
    const int lane = tid & 31;
    const int wid  = tid >> 5;
    const int m_base = blockIdx.x * BM;     // 0 or 128
    const int n_base = blockIdx.y * BN;
    const int wm = (wid >> 2) * 64;
    const int wn = (wid & 3) * 32;

    float acc[4][4][4] = {};
    float4 stA[4], stB[4];

    // gmem load of one K-chunk into staging regs
    auto ldg = [&](int k0) {
        #pragma unroll
        for (int i = 0; i < 4; i++) {
            int idx = i * 256 + tid;
            int r = idx >> 3, c = idx & 7;
            stA[i] = *reinterpret_cast<const float4*>(X + (size_t)(m_base + r) * NH + k0 + c * 4);
            int v = n_base + r;
            stB[i] = (v < NV)
                ? *reinterpret_cast<const float4*>(W + (size_t)v * NH + k0 + c * 4)
                : make_float4(0.f, 0.f, 0.f, 0.f);
        }
    };
    // convert + store staging regs into smem buffer bsel
    auto sts = [&](int bsel) {
        char* base = sm + bsel * BUF;
        #pragma unroll
        for (int i = 0; i < 4; i++) {
            int idx = i * 256 + tid;
            int r = idx >> 3, c = idx & 7;
            unsigned off = r * TSTR + c * 8;
            cvt_store_f16(base, off, stA[i]);
            cvt_store_f16(base + TILE, off, stB[i]);
        }
    };
    auto compute = [&](int bsel) {
        const unsigned Ah = smb + bsel * BUF;
        const unsigned Bh = Ah + TILE;
        const int arow = wm + (lane & 15);
        const int nrow = wn + (lane & 7) + ((lane & 16) ? 8 : 0);
        #pragma unroll
        for (int kk = 0; kk < BK; kk += 16) {
            const unsigned akb = (kk + ((lane & 16) ? 8 : 0)) * 2;
            const unsigned bkb = (kk + ((lane & 8)  ? 8 : 0)) * 2;
            unsigned ah[4][4], bh[4][2];
            #pragma unroll
            for (int mt = 0; mt < 4; mt++) {
                unsigned ad = Ah + (unsigned)(arow + mt * 16) * TSTR + akb;
                ldsm_x4(ah[mt], ad);
            }
            #pragma unroll
            for (int jp = 0; jp < 2; jp++) {
                unsigned bd = Bh + (unsigned)(nrow + jp * 16) * TSTR + bkb;
                unsigned r[4];
                ldsm_x4(r, bd);
                bh[jp * 2][0] = r[0]; bh[jp * 2][1] = r[1];
                bh[jp * 2 + 1][0] = r[2]; bh[jp * 2 + 1][1] = r[3];
            }
            #pragma unroll
            for (int mt = 0; mt < 4; mt++)
                #pragma unroll
                for (int nt = 0; nt < 4; nt++)
                    mma_f16(acc[mt][nt], ah[mt], bh[nt]);
        }
    };

    ldg(0);
    sts(0);
    __syncthreads();
    #pragma unroll 1
    for (int ck = 1; ck <= NH / BK; ck++) {
        if (ck < NH / BK) ldg(ck * BK);
        compute((ck - 1) & 1);
        if (ck < NH / BK) sts(ck & 1);
        __syncthreads();
    }

    // epilogue
    for (int i = tid; i < BN; i += 256) {
        int v = n_base + i;
        s_bias[i] = (v < NV) ? bias[v] : 0.f;
    }
    __syncthreads();

    const int g  = lane >> 2;
    const int t2 = (lane & 3) * 2;
    #pragma unroll
    for (int mt = 0; mt < 4; mt++) {
        const int m0 = m_base + wm + mt * 16 + g;
        float* row0 = out + (size_t)m0 * NV;
        float* row1 = out + (size_t)(m0 + 8) * NV;
        #pragma unroll
        for (int nt = 0; nt < 4; nt++) {
            const int ncol = wn + nt * 8 + t2;
            const int v = n_base + ncol;
            if (v < NV) {
                const float b0 = s_bias[ncol];
                row0[v] = acc[mt][nt][0] + b0;
                row1[v] = acc[mt][nt][2] + b0;
                if (v + 1 < NV) {
                    const float b1 = s_bias[ncol + 1];
                    row0[v + 1] = acc[mt][nt][1] + b1;
                    row1[v + 1] = acc[mt][nt][3] + b1;
                }
            }
        }
    }
}

// ---------------------------------------------------------------------------
// K3: fused softmax + p_gen mix + scatter + log (row in SMEM).
// exp computed once (cached in smem during the sum pass).
// ---------------------------------------------------------------------------
__global__ void finalize_kernel(float* __restrict__ out,
                                const float* __restrict__ attn,
                                const void* __restrict__ ids_raw) {
    extern __shared__ float row[];
    __shared__ float red[32];
    __shared__ float s_bcast;

    const int b = blockIdx.x;
    const int tid = threadIdx.x;   // 1024
    float* o = out + (size_t)b * NV;

    float m = -INFINITY;
    for (int v = tid; v < NV; v += 1024) {
        float t = o[v];
        row[v] = t;
        m = fmaxf(m, t);
    }
    m = warp_reduce_max(m);
    if ((tid & 31) == 0) red[tid >> 5] = m;
    __syncthreads();
    if (tid < 32) {
        float t = warp_reduce_max(red[tid]);
        if (tid == 0) s_bcast = t;
    }
    __syncthreads();
    m = s_bcast;

    float sum = 0.f;
    for (int v = tid; v < NV; v += 1024) {
        float e = __expf(row[v] - m);
        row[v] = e;
        sum += e;
    }
    sum = warp_reduce_sum(sum);
    __syncthreads();
    if ((tid & 31) == 0) red[tid >> 5] = sum;
    __syncthreads();
    if (tid < 32) {
        float t = warp_reduce_sum(red[tid]);
        if (tid == 0) s_bcast = t;
    }
    __syncthreads();
    sum = s_bcast;

    const float pg = g_pgen[b];
    const float scale = pg / sum;

    for (int v = tid; v < NV; v += 1024) row[v] *= scale;
    __syncthreads();

    if (tid < NS) {
        int id;
        if (g_ids_is64)
            id = (int)reinterpret_cast<const long long*>(ids_raw)[(size_t)b * NS + tid];
        else
            id = reinterpret_cast<const int*>(ids_raw)[(size_t)b * NS + tid];
        atomicAdd(&row[id], (1.f - pg) * attn[b * NS + tid]);
    }
    __syncthreads();

    for (int v = tid; v < NV; v += 1024) o[v] = logf(row[v] + 1e-40f);
}

// ---------------------------------------------------------------------------
// Launch
// ---------------------------------------------------------------------------
extern "C" void kernel_launch(void* const* d_in, const int* in_sizes, int n_in,
                              void* d_out, int out_size) {
    const float* x      = (const float*)d_in[0];
    const float* embed  = (const float*)d_in[1];
    const float* hidden = (const float*)d_in[2];
    const float* enc    = (const float*)d_in[3];
    const float* attn   = (const float*)d_in[4];
    const void*  ids    = d_in[5];
    const float* proj_w = (const float*)d_in[6];
    const float* proj_b = (const float*)d_in[7];
    const float* pgen_w = (const float*)d_in[8];
    const float* pgen_b = (const float*)d_in[9];
    float* out = (float*)d_out;

    detect_ids_kernel<<<1, 256>>>((const int*)ids);

    dim3 gctx(NB, SCHUNKS);
    ctx_partial_kernel<<<gctx, 256>>>(attn, enc, pgen_w);
    pgen_kernel<<<NB, 256>>>(hidden, embed, pgen_w, pgen_b);

    cudaFuncSetAttribute(gemm_mma_kernel,
                         cudaFuncAttributeMaxDynamicSharedMemorySize, GSMEM);
    dim3 gg(NB / BM, (NV + BN - 1) / BN);   // (2, 393): M-halves adjacent -> L2 reuse of W
    gemm_mma_kernel<<<gg, 256, GSMEM>>>(x, proj_w, proj_b, out);

    const int smem_bytes = NV * sizeof(float);
    cudaFuncSetAttribute(finalize_kernel,
                         cudaFuncAttributeMaxDynamicSharedMemorySize, smem_bytes);
    finalize_kernel<<<NB, 1024, smem_bytes>>>(out, attn, ids);
}